// round 8
// baseline (speedup 1.0000x reference)
#include <cuda_runtime.h>
#include <cstdint>

typedef unsigned long long ull;

// ---------------------------------------------------------------------------
// Packed f32x2 helpers (Blackwell packed-fp32 pipe — only reachable via PTX)
// ---------------------------------------------------------------------------
__device__ __forceinline__ ull ffma2(ull a, ull b, ull c) {
    ull d;
    asm("fma.rn.f32x2 %0, %1, %2, %3;" : "=l"(d) : "l"(a), "l"(b), "l"(c));
    return d;
}
__device__ __forceinline__ float f2lo(ull v) { return __uint_as_float((unsigned)(v & 0xffffffffu)); }
__device__ __forceinline__ float f2hi(ull v) { return __uint_as_float((unsigned)(v >> 32)); }
__device__ __forceinline__ ull fpack(float lo, float hi) {
    return ((ull)__float_as_uint(hi) << 32) | (ull)__float_as_uint(lo);
}
__device__ __forceinline__ ull fdup(float v) {
    unsigned u = __float_as_uint(v);
    return ((ull)u << 32) | (ull)u;
}

#define NEG_INF __int_as_float(0xff800000)

// ---------------------------------------------------------------------------
// Per-point prep: packed |Y| for both branches (+0.25 lo lane, -0.25 hi lane)
// with the odd-parity coord-0 flip, plus sign bitmasks (bit (7-i) set where
// mask_i < 0, including the parity flip on coord 0).
// ---------------------------------------------------------------------------
__device__ __forceinline__ void prep_point(const float* __restrict__ Xp,
                                           ull ya2[8], unsigned& nbp, unsigned& nbm) {
    float4 x0 = *reinterpret_cast<const float4*>(Xp);
    float4 x1 = *reinterpret_cast<const float4*>(Xp + 4);
    float x[8] = {x0.x, x0.y, x0.z, x0.w, x1.x, x1.y, x1.z, x1.w};
    float yp[8], ym[8];
    unsigned bp = 0u, bm = 0u;
#pragma unroll
    for (int i = 0; i < 8; i++) {
        float a = x[i] + 0.25f;
        float b = x[i] - 0.25f;
        bp |= (a < 0.0f ? 1u : 0u) << (7 - i);
        bm |= (b < 0.0f ? 1u : 0u) << (7 - i);
        yp[i] = fabsf(a);
        ym[i] = fabsf(b);
    }
    if (__popc(bp) & 1) { yp[0] = -yp[0]; bp ^= 0x80u; }
    if (__popc(bm) & 1) { ym[0] = -ym[0]; bm ^= 0x80u; }
#pragma unroll
    for (int i = 0; i < 8; i++) ya2[i] = fpack(yp[i], ym[i]);
    nbp = bp;
    nbm = bm;
}

// ---------------------------------------------------------------------------
// Epilogue: reconstruct both branch errors/values, pick branch, index lookups
// (grid_idx_map applied ANALYTICALLY: gim[j] = j - 32768 by construction —
// the int16 input is promoted to int32 by the harness so cannot be read as
// shorts), write outputs. idx region is float32 (round-4 NaN evidence).
// ---------------------------------------------------------------------------
__device__ __forceinline__ void finish_point(
    int p, const ull* __restrict__ g2, int G,
    const ull ya2[8], unsigned nbp, unsigned nbm, int qp, int qm,
    const int* __restrict__ idx_map, const int* __restrict__ allcombo,
    float* __restrict__ out_vals, float* __restrict__ out_idx_f) {
    const ull* gqp = g2 + (size_t)qp * 8;
    const ull* gqm = g2 + (size_t)qm * 8;
    float pv[8], mv[8];
    float ep2 = 0.0f, em2 = 0.0f;
#pragma unroll
    for (int i = 0; i < 8; i++) {
        float gp_ = f2lo(gqp[i]) * 0.5f;  // stored as 2*g; *0.5 exact
        float gm_ = f2lo(gqm[i]) * 0.5f;
        float dp = f2lo(ya2[i]) - gp_;    // == +/-(Y - vals): square bit-identical
        float dm = f2hi(ya2[i]) - gm_;
        ep2 = fmaf(dp, dp, ep2);
        em2 = fmaf(dm, dm, em2);
        pv[i] = ((nbp >> (7 - i)) & 1u) ? -gp_ : gp_;
        mv[i] = ((nbm >> (7 - i)) & 1u) ? -gm_ : gm_;
    }
    bool which = sqrtf(ep2) < sqrtf(em2);   // matches reference: sqrt then strict <

    int rowp = __ldg(&idx_map[nbp]);
    int rowm = __ldg(&idx_map[nbm]);
    int pi = __ldg(&allcombo[(size_t)rowp * G + qp]);
    int mi = __ldg(&allcombo[(size_t)rowm * G + qm]);
    int j = which ? (pi + 32768) : mi;
    if (j > 65535) j = 65535;               // JAX clamps OOB gather indices
    int idx = j - 32768;                    // == grid_idx_map[j] analytically

    float ov[8];
#pragma unroll
    for (int i = 0; i < 8; i++) ov[i] = which ? (pv[i] - 0.25f) : (mv[i] + 0.25f);
    float4* ovp = reinterpret_cast<float4*>(out_vals + (size_t)p * 8);
    ovp[0] = make_float4(ov[0], ov[1], ov[2], ov[3]);
    ovp[1] = make_float4(ov[4], ov[5], ov[6], ov[7]);

    out_idx_f[p] = (float)idx;
}

// ---------------------------------------------------------------------------
// Main kernel: ONE point per thread (512-thread CTAs) so the grid carries
// 4096 warps (~28/SM) — round-7 showed total residency, not smem, was the
// occupancy cap at 2 points/thread. Both branches packed in f32x2; single
// 8-deep FFMA2 chain per iter initialized with (-n,-n) (latency hidden by
// TLP now, so no ILP split needed). Grid loop warp-uniform -> LDS broadcast.
// ---------------------------------------------------------------------------
__global__ void __launch_bounds__(512, 2)
e8p12_kernel(const float* __restrict__ X,
             const float* __restrict__ grid,
             const float* __restrict__ gnorm,
             const int*   __restrict__ allcombo,
             const int*   __restrict__ idx_map,
             float* __restrict__ out_vals,
             float* __restrict__ out_idx_f,
             int N, int G) {
    extern __shared__ ull sm_u64[];
    ull* g2 = sm_u64;                    // [G*8]  packed (2g, 2g), 64B/entry
    ull* n2 = sm_u64 + (size_t)G * 8;    // [G]    packed (-n, -n)

    const int tid = threadIdx.x;
    for (int jj = tid; jj < G * 8; jj += blockDim.x) g2[jj] = fdup(2.0f * grid[jj]);
    for (int jj = tid; jj < G; jj += blockDim.x) n2[jj] = fdup(-gnorm[jj]);
    __syncthreads();

    const int p = blockIdx.x * (int)blockDim.x + tid;
    if (p >= N) return;

    ull ya[8];
    unsigned nbp, nbm;
    prep_point(X + (size_t)p * 8, ya, nbp, nbm);

    float bp = NEG_INF, bm = NEG_INF;
    int qp = 0, qm = 0;

#pragma unroll 4
    for (int g = 0; g < G; ++g) {
        const ulonglong2* gp2 =
            reinterpret_cast<const ulonglong2*>(g2 + (size_t)g * 8);
        const ulonglong2 c01 = gp2[0];   // LDS.128 broadcast
        const ulonglong2 c23 = gp2[1];
        const ulonglong2 c45 = gp2[2];
        const ulonglong2 c67 = gp2[3];
        const ull nn = n2[g];

        ull a = ffma2(ya[0], c01.x, nn);
        a = ffma2(ya[1], c01.y, a);
        a = ffma2(ya[2], c23.x, a);
        a = ffma2(ya[3], c23.y, a);
        a = ffma2(ya[4], c45.x, a);
        a = ffma2(ya[5], c45.y, a);
        a = ffma2(ya[6], c67.x, a);
        a = ffma2(ya[7], c67.y, a);

        const float sp = f2lo(a), sm = f2hi(a);
        if (sp > bp) { bp = sp; qp = g; }
        if (sm > bm) { bm = sm; qm = g; }
    }

    finish_point(p, g2, G, ya, nbp, nbm, qp, qm,
                 idx_map, allcombo, out_vals, out_idx_f);
}

// ---------------------------------------------------------------------------
// Launch. Inputs (metadata order):
//   0: X              float32 [N,8]
//   1: grid_part      float32 [G,8]
//   2: grid_part_norm float32 [G]
//   3: allcombo_idx   int32   [128,G]
//   4: idx_map        int32   [256]
//   5: int_map        int32   [8]      (unused: bit packing hard-coded)
//   6: grid_idx_map   int16->int32 promoted (NOT read; computed analytically)
//
// Output layout (pinned by rounds 0-6):
//   final_vals  float32 [N,8] at element 0   (bit-exact)
//   final_idxs  float32 [N]   at element 8N
// ---------------------------------------------------------------------------
extern "C" void kernel_launch(void* const* d_in, const int* in_sizes, int n_in,
                              void* d_out, int out_size) {
    const float* X        = (const float*)d_in[0];
    const float* grid     = (const float*)d_in[1];
    const float* gnorm    = (const float*)d_in[2];
    const int*   allcombo = (const int*)d_in[3];
    const int*   idx_map  = (const int*)d_in[4];

    const int N = in_sizes[0] / 8;
    const int G = in_sizes[2];

    float* out_vals  = (float*)d_out;
    float* out_idx_f = (float*)d_out + (size_t)N * 8;

    const size_t smem = (size_t)G * 9 * sizeof(ull);   // ~99 KB for G~1369
    cudaFuncSetAttribute(e8p12_kernel,
                         cudaFuncAttributeMaxDynamicSharedMemorySize, (int)smem);

    const int threads = 512;                           // 1 point per thread
    const int ctas = (N + threads - 1) / threads;      // 256 CTAs for N=131072

    e8p12_kernel<<<ctas, threads, smem>>>(X, grid, gnorm, allcombo, idx_map,
                                          out_vals, out_idx_f, N, G);
}

// round 11
// speedup vs baseline: 1.1861x; 1.1861x over previous
#include <cuda_runtime.h>
#include <cstdint>

typedef unsigned long long ull;

// ---------------------------------------------------------------------------
// Packed f32x2 helpers (Blackwell packed-fp32 pipe — only reachable via PTX)
// ---------------------------------------------------------------------------
__device__ __forceinline__ ull ffma2(ull a, ull b, ull c) {
    ull d;
    asm("fma.rn.f32x2 %0, %1, %2, %3;" : "=l"(d) : "l"(a), "l"(b), "l"(c));
    return d;
}
__device__ __forceinline__ float f2lo(ull v) { return __uint_as_float((unsigned)(v & 0xffffffffu)); }
__device__ __forceinline__ float f2hi(ull v) { return __uint_as_float((unsigned)(v >> 32)); }
__device__ __forceinline__ ull fpack(float lo, float hi) {
    return ((ull)__float_as_uint(hi) << 32) | (ull)__float_as_uint(lo);
}
__device__ __forceinline__ ull fdup(float v) {
    unsigned u = __float_as_uint(v);
    return ((ull)u << 32) | (ull)u;
}

#define NEG_INF __int_as_float(0xff800000)

// ---------------------------------------------------------------------------
// Per-point prep: |Y| for both branches with the odd-parity coord-0 flip and
// sign bitmasks (bit (7-i) set where mask_i < 0, incl. the parity flip).
// Results duplicated into both f32x2 lanes (lane pair now = grid-entry pair).
// ---------------------------------------------------------------------------
__device__ __forceinline__ void prep_point(const float* __restrict__ Xp,
                                           ull ypd[8], ull ymd[8],
                                           unsigned& nbp, unsigned& nbm) {
    float4 x0 = *reinterpret_cast<const float4*>(Xp);
    float4 x1 = *reinterpret_cast<const float4*>(Xp + 4);
    float x[8] = {x0.x, x0.y, x0.z, x0.w, x1.x, x1.y, x1.z, x1.w};
    float yp[8], ym[8];
    unsigned bp = 0u, bm = 0u;
#pragma unroll
    for (int i = 0; i < 8; i++) {
        float a = x[i] + 0.25f;
        float b = x[i] - 0.25f;
        bp |= (a < 0.0f ? 1u : 0u) << (7 - i);
        bm |= (b < 0.0f ? 1u : 0u) << (7 - i);
        yp[i] = fabsf(a);
        ym[i] = fabsf(b);
    }
    if (__popc(bp) & 1) { yp[0] = -yp[0]; bp ^= 0x80u; }
    if (__popc(bm) & 1) { ym[0] = -ym[0]; bm ^= 0x80u; }
#pragma unroll
    for (int i = 0; i < 8; i++) { ypd[i] = fdup(yp[i]); ymd[i] = fdup(ym[i]); }
    nbp = bp;
    nbm = bm;
}

// Read coord i of entry q from the pair layout (stored as 2*g; *0.5 exact).
__device__ __forceinline__ float grid_coord(const ull* __restrict__ g2p,
                                            int q, int i) {
    ull w = g2p[(size_t)(q >> 1) * 8 + i];
    return ((q & 1) ? f2hi(w) : f2lo(w)) * 0.5f;
}

// ---------------------------------------------------------------------------
// Epilogue: reconstruct both branch errors/values, pick branch, index lookups
// (grid_idx_map applied ANALYTICALLY: gim[j] = j - 32768 by construction —
// the int16 input is promoted to int32 by the harness), write outputs.
// idx region is float32 at element 8N (round-4 NaN evidence).
// ---------------------------------------------------------------------------
__device__ __forceinline__ void finish_point(
    int p, const ull* __restrict__ g2p, int G,
    const ull ypd[8], const ull ymd[8],
    unsigned nbp, unsigned nbm, int qp, int qm,
    const int* __restrict__ idx_map, const int* __restrict__ allcombo,
    float* __restrict__ out_vals, float* __restrict__ out_idx_f) {
    float pv[8], mv[8];
    float ep2 = 0.0f, em2 = 0.0f;
#pragma unroll
    for (int i = 0; i < 8; i++) {
        float gp_ = grid_coord(g2p, qp, i);
        float gm_ = grid_coord(g2p, qm, i);
        float dp = f2lo(ypd[i]) - gp_;    // == +/-(Y - vals): square bit-identical
        float dm = f2lo(ymd[i]) - gm_;
        ep2 = fmaf(dp, dp, ep2);
        em2 = fmaf(dm, dm, em2);
        pv[i] = ((nbp >> (7 - i)) & 1u) ? -gp_ : gp_;
        mv[i] = ((nbm >> (7 - i)) & 1u) ? -gm_ : gm_;
    }
    bool which = sqrtf(ep2) < sqrtf(em2);   // matches reference: sqrt then strict <

    int rowp = __ldg(&idx_map[nbp]);
    int rowm = __ldg(&idx_map[nbm]);
    int pi = __ldg(&allcombo[(size_t)rowp * G + qp]);
    int mi = __ldg(&allcombo[(size_t)rowm * G + qm]);
    int j = which ? (pi + 32768) : mi;
    if (j > 65535) j = 65535;               // JAX clamps OOB gather indices
    int idx = j - 32768;                    // == grid_idx_map[j] analytically

    float ov[8];
#pragma unroll
    for (int i = 0; i < 8; i++) ov[i] = which ? (pv[i] - 0.25f) : (mv[i] + 0.25f);
    float4* ovp = reinterpret_cast<float4*>(out_vals + (size_t)p * 8);
    ovp[0] = make_float4(ov[0], ov[1], ov[2], ov[3]);
    ovp[1] = make_float4(ov[4], ov[5], ov[6], ov[7]);

    out_idx_f[p] = (float)idx;
}

// ---------------------------------------------------------------------------
// Main kernel: one point per thread; f32x2 lanes carry a PAIR of grid entries
// (even entry in lo, odd in hi) -> 2.5 LDS + 8 FFMA2 per entry (round-8 ncu
// showed LDS was the binding pipe at 5 LDS/entry). Point data duplicated into
// both lanes once at prep. Smem halves to ~49 KB -> 4 CTAs/SM, 32 warps/SM.
// Chunked CTA->point assignment balances work across all 148 SMs.
// Per-entry arithmetic = same 8-deep fma chain init -n as all passing rounds.
// ---------------------------------------------------------------------------
__global__ void __launch_bounds__(256, 4)
e8p12_kernel(const float* __restrict__ X,
             const float* __restrict__ grid,
             const float* __restrict__ gnorm,
             const int*   __restrict__ allcombo,
             const int*   __restrict__ idx_map,
             float* __restrict__ out_vals,
             float* __restrict__ out_idx_f,
             int N, int G, int G2, int chunk) {
    extern __shared__ ull sm_u64[];
    ull* g2p = sm_u64;                     // [G2*8] coord words (2g_e0, 2g_e1)
    ull* n2  = sm_u64 + (size_t)G2 * 8;    // [G2]   (-n_e0, -n_e1)

    const int tid = threadIdx.x;
    for (int j = tid; j < G2 * 8; j += blockDim.x) {
        int k = j >> 3, i = j & 7;
        int e0 = 2 * k, e1 = 2 * k + 1;
        float lo = 2.0f * grid[(size_t)e0 * 8 + i];
        float hi = (e1 < G) ? 2.0f * grid[(size_t)e1 * 8 + i] : 0.0f;
        g2p[j] = fpack(lo, hi);
    }
    for (int k = tid; k < G2; k += blockDim.x) {
        int e0 = 2 * k, e1 = 2 * k + 1;
        float lo = -gnorm[e0];
        float hi = (e1 < G) ? -gnorm[e1] : NEG_INF;  // pad entry never wins
        n2[k] = fpack(lo, hi);
    }
    __syncthreads();

    const int p = blockIdx.x * chunk + tid;
    if (tid >= chunk || p >= N) return;

    ull ypd[8], ymd[8];
    unsigned nbp, nbm;
    prep_point(X + (size_t)p * 8, ypd, ymd, nbp, nbm);

    float bp = NEG_INF, bm = NEG_INF;
    int qp = 0, qm = 0;

#pragma unroll 2
    for (int k = 0; k < G2; ++k) {
        const ulonglong2* gq =
            reinterpret_cast<const ulonglong2*>(g2p + (size_t)k * 8);
        const ulonglong2 c01 = gq[0];   // LDS.128 broadcast
        const ulonglong2 c23 = gq[1];
        const ulonglong2 c45 = gq[2];
        const ulonglong2 c67 = gq[3];
        const ull nn = n2[k];

        ull ap = ffma2(ypd[0], c01.x, nn);
        ull am = ffma2(ymd[0], c01.x, nn);
        ap = ffma2(ypd[1], c01.y, ap);  am = ffma2(ymd[1], c01.y, am);
        ap = ffma2(ypd[2], c23.x, ap);  am = ffma2(ymd[2], c23.x, am);
        ap = ffma2(ypd[3], c23.y, ap);  am = ffma2(ymd[3], c23.y, am);
        ap = ffma2(ypd[4], c45.x, ap);  am = ffma2(ymd[4], c45.x, am);
        ap = ffma2(ypd[5], c45.y, ap);  am = ffma2(ymd[5], c45.y, am);
        ap = ffma2(ypd[6], c67.x, ap);  am = ffma2(ymd[6], c67.x, am);
        ap = ffma2(ypd[7], c67.y, ap);  am = ffma2(ymd[7], c67.y, am);

        const int e0 = 2 * k, e1 = 2 * k + 1;
        const float s0p = f2lo(ap), s1p = f2hi(ap);
        const float s0m = f2lo(am), s1m = f2hi(am);
        // sequential order preserved: even entry checked before odd, strict >
        if (s0p > bp) { bp = s0p; qp = e0; }
        if (s1p > bp) { bp = s1p; qp = e1; }
        if (s0m > bm) { bm = s0m; qm = e0; }
        if (s1m > bm) { bm = s1m; qm = e1; }
    }

    finish_point(p, g2p, G, ypd, ymd, nbp, nbm, qp, qm,
                 idx_map, allcombo, out_vals, out_idx_f);
}

// ---------------------------------------------------------------------------
// Launch. Inputs (metadata order):
//   0: X              float32 [N,8]
//   1: grid_part      float32 [G,8]
//   2: grid_part_norm float32 [G]
//   3: allcombo_idx   int32   [128,G]
//   4: idx_map        int32   [256]
//   5: int_map        int32   [8]      (unused: bit packing hard-coded)
//   6: grid_idx_map   int16->int32 promoted (NOT read; computed analytically)
//
// Output layout (pinned by rounds 0-6):
//   final_vals  float32 [N,8] at element 0   (bit-exact)
//   final_idxs  float32 [N]   at element 8N
// ---------------------------------------------------------------------------
extern "C" void kernel_launch(void* const* d_in, const int* in_sizes, int n_in,
                              void* d_out, int out_size) {
    const float* X        = (const float*)d_in[0];
    const float* grid     = (const float*)d_in[1];
    const float* gnorm    = (const float*)d_in[2];
    const int*   allcombo = (const int*)d_in[3];
    const int*   idx_map  = (const int*)d_in[4];

    const int N = in_sizes[0] / 8;
    const int G = in_sizes[2];
    const int G2 = (G + 1) / 2;

    float* out_vals  = (float*)d_out;
    float* out_idx_f = (float*)d_out + (size_t)N * 8;

    const size_t smem = (size_t)G2 * 9 * sizeof(ull);   // ~49 KB for G~1369
    cudaFuncSetAttribute(e8p12_kernel,
                         cudaFuncAttributeMaxDynamicSharedMemorySize, (int)smem);

    const int threads = 256;
    // Balanced grid: 148 SMs x 4 CTAs/SM slots, chunked point assignment.
    int ctas = 148 * 4;
    int chunk = (N + ctas - 1) / ctas;
    if (chunk > threads) {                 // very large N fallback
        chunk = threads;
        ctas = (N + threads - 1) / threads;
    }

    e8p12_kernel<<<ctas, threads, smem>>>(X, grid, gnorm, allcombo, idx_map,
                                          out_vals, out_idx_f, N, G, G2, chunk);
}

// round 14
// speedup vs baseline: 1.2991x; 1.0952x over previous
#include <cuda_runtime.h>
#include <cstdint>

typedef unsigned long long ull;

// ---------------------------------------------------------------------------
// Packed f32x2 helpers (Blackwell packed-fp32 pipe — only reachable via PTX).
// NOTE: only fma/add/mul have .f32x2 forms; max does NOT (round-12 ptxas).
// ---------------------------------------------------------------------------
__device__ __forceinline__ ull ffma2(ull a, ull b, ull c) {
    ull d;
    asm("fma.rn.f32x2 %0, %1, %2, %3;" : "=l"(d) : "l"(a), "l"(b), "l"(c));
    return d;
}
__device__ __forceinline__ float f2lo(ull v) { return __uint_as_float((unsigned)(v & 0xffffffffu)); }
__device__ __forceinline__ float f2hi(ull v) { return __uint_as_float((unsigned)(v >> 32)); }
__device__ __forceinline__ ull fpack(float lo, float hi) {
    return ((ull)__float_as_uint(hi) << 32) | (ull)__float_as_uint(lo);
}
__device__ __forceinline__ ull fdup(float v) {
    unsigned u = __float_as_uint(v);
    return ((ull)u << 32) | (ull)u;
}

#define NEG_INF __int_as_float(0xff800000)
#define GU 16   // pairs per group for deferred-index argmax

// ---------------------------------------------------------------------------
// One branch's packed pair-score: 8-deep fma.rn.f32x2 chain init (-n,-n).
// Used by BOTH the main loop and the rescan -> bitwise-identical results.
// ---------------------------------------------------------------------------
__device__ __forceinline__ ull score_chain(const ull* __restrict__ g2p,
                                           const ull* __restrict__ n2,
                                           int k, const ull y[8]) {
    const ulonglong2* gq = reinterpret_cast<const ulonglong2*>(g2p + (size_t)k * 8);
    const ulonglong2 c01 = gq[0];   // LDS.128 broadcast (warp-uniform address)
    const ulonglong2 c23 = gq[1];
    const ulonglong2 c45 = gq[2];
    const ulonglong2 c67 = gq[3];
    ull a = ffma2(y[0], c01.x, n2[k]);
    a = ffma2(y[1], c01.y, a);
    a = ffma2(y[2], c23.x, a);
    a = ffma2(y[3], c23.y, a);
    a = ffma2(y[4], c45.x, a);
    a = ffma2(y[5], c45.y, a);
    a = ffma2(y[6], c67.x, a);
    a = ffma2(y[7], c67.y, a);
    return a;
}

// ---------------------------------------------------------------------------
// Per-point prep: |Y| for both branches with the odd-parity coord-0 flip and
// sign bitmasks (bit (7-i) set where mask_i < 0, incl. the parity flip).
// Duplicated into both f32x2 lanes (lane pair = grid-entry pair).
// ---------------------------------------------------------------------------
__device__ __forceinline__ void prep_point(const float* __restrict__ Xp,
                                           ull ypd[8], ull ymd[8],
                                           unsigned& nbp, unsigned& nbm) {
    float4 x0 = *reinterpret_cast<const float4*>(Xp);
    float4 x1 = *reinterpret_cast<const float4*>(Xp + 4);
    float x[8] = {x0.x, x0.y, x0.z, x0.w, x1.x, x1.y, x1.z, x1.w};
    float yp[8], ym[8];
    unsigned bp = 0u, bm = 0u;
#pragma unroll
    for (int i = 0; i < 8; i++) {
        float a = x[i] + 0.25f;
        float b = x[i] - 0.25f;
        bp |= (a < 0.0f ? 1u : 0u) << (7 - i);
        bm |= (b < 0.0f ? 1u : 0u) << (7 - i);
        yp[i] = fabsf(a);
        ym[i] = fabsf(b);
    }
    if (__popc(bp) & 1) { yp[0] = -yp[0]; bp ^= 0x80u; }
    if (__popc(bm) & 1) { ym[0] = -ym[0]; bm ^= 0x80u; }
#pragma unroll
    for (int i = 0; i < 8; i++) { ypd[i] = fdup(yp[i]); ymd[i] = fdup(ym[i]); }
    nbp = bp;
    nbm = bm;
}

// Read coord i of entry q from the pair layout (stored as 2*g; *0.5 exact).
__device__ __forceinline__ float grid_coord(const ull* __restrict__ g2p,
                                            int q, int i) {
    ull w = g2p[(size_t)(q >> 1) * 8 + i];
    return ((q & 1) ? f2hi(w) : f2lo(w)) * 0.5f;
}

// ---------------------------------------------------------------------------
// Epilogue: reconstruct both branch errors/values, pick branch, index lookups
// (grid_idx_map applied ANALYTICALLY: gim[j] = j - 32768 by construction —
// the int16 input is promoted to int32 by the harness), write outputs.
// idx region is float32 at element 8N (round-4 NaN evidence).
// ---------------------------------------------------------------------------
__device__ __forceinline__ void finish_point(
    int p, const ull* __restrict__ g2p, int G,
    const ull ypd[8], const ull ymd[8],
    unsigned nbp, unsigned nbm, int qp, int qm,
    const int* __restrict__ idx_map, const int* __restrict__ allcombo,
    float* __restrict__ out_vals, float* __restrict__ out_idx_f) {
    float pv[8], mv[8];
    float ep2 = 0.0f, em2 = 0.0f;
#pragma unroll
    for (int i = 0; i < 8; i++) {
        float gp_ = grid_coord(g2p, qp, i);
        float gm_ = grid_coord(g2p, qm, i);
        float dp = f2lo(ypd[i]) - gp_;    // == +/-(Y - vals): square bit-identical
        float dm = f2lo(ymd[i]) - gm_;
        ep2 = fmaf(dp, dp, ep2);
        em2 = fmaf(dm, dm, em2);
        pv[i] = ((nbp >> (7 - i)) & 1u) ? -gp_ : gp_;
        mv[i] = ((nbm >> (7 - i)) & 1u) ? -gm_ : gm_;
    }
    bool which = sqrtf(ep2) < sqrtf(em2);   // matches reference: sqrt then strict <

    int rowp = __ldg(&idx_map[nbp]);
    int rowm = __ldg(&idx_map[nbm]);
    int pi = __ldg(&allcombo[(size_t)rowp * G + qp]);
    int mi = __ldg(&allcombo[(size_t)rowm * G + qm]);
    int j = which ? (pi + 32768) : mi;
    if (j > 65535) j = 65535;               // JAX clamps OOB gather indices
    int idx = j - 32768;                    // == grid_idx_map[j] analytically

    float ov[8];
#pragma unroll
    for (int i = 0; i < 8; i++) ov[i] = which ? (pv[i] - 0.25f) : (mv[i] + 0.25f);
    float4* ovp = reinterpret_cast<float4*>(out_vals + (size_t)p * 8);
    ovp[0] = make_float4(ov[0], ov[1], ov[2], ov[3]);
    ovp[1] = make_float4(ov[4], ov[5], ov[6], ov[7]);

    out_idx_f[p] = (float)idx;
}

// ---------------------------------------------------------------------------
// Main kernel: one point/thread; f32x2 lanes carry a PAIR of grid entries.
// Argmax via per-lane fmaxf group-max (FMNMX, lat-4 alu op, no predicates in
// the hot loop — round-11 showed alu=37.4% from FSETP/SEL bookkeeping) +
// per-group scalar merge + one-time rescan of the winning 16-pair group using
// the bitwise-identical score chain. Ties are measure-zero (5 rounds of
// reordered accumulation gave bit-exact vals), so unique-max => exact argmax.
// ---------------------------------------------------------------------------
__global__ void __launch_bounds__(256, 4)
e8p12_kernel(const float* __restrict__ X,
             const float* __restrict__ grid,
             const float* __restrict__ gnorm,
             const int*   __restrict__ allcombo,
             const int*   __restrict__ idx_map,
             float* __restrict__ out_vals,
             float* __restrict__ out_idx_f,
             int N, int G, int G2r, int chunk) {
    extern __shared__ ull sm_u64[];
    ull* g2p = sm_u64;                      // [G2r*8] coord words (2g_e0, 2g_e1)
    ull* n2  = sm_u64 + (size_t)G2r * 8;    // [G2r]   (-n_e0, -n_e1); pad=-inf

    const int tid = threadIdx.x;
    for (int j = tid; j < G2r * 8; j += blockDim.x) {
        int k = j >> 3, i = j & 7;
        int e0 = 2 * k, e1 = 2 * k + 1;
        float lo = (e0 < G) ? 2.0f * grid[(size_t)e0 * 8 + i] : 0.0f;
        float hi = (e1 < G) ? 2.0f * grid[(size_t)e1 * 8 + i] : 0.0f;
        g2p[j] = fpack(lo, hi);
    }
    for (int k = tid; k < G2r; k += blockDim.x) {
        int e0 = 2 * k, e1 = 2 * k + 1;
        float lo = (e0 < G) ? -gnorm[e0] : NEG_INF;   // pad never wins
        float hi = (e1 < G) ? -gnorm[e1] : NEG_INF;
        n2[k] = fpack(lo, hi);
    }
    __syncthreads();

    const int p = blockIdx.x * chunk + tid;
    if (tid >= chunk || p >= N) return;

    ull ypd[8], ymd[8];
    unsigned nbp, nbm;
    prep_point(X + (size_t)p * 8, ypd, ymd, nbp, nbm);

    float gbvp = NEG_INF, gbvm = NEG_INF;
    int gidp = 0, gidm = 0;

    for (int k0 = 0; k0 < G2r; k0 += GU) {
        float plo = NEG_INF, phi = NEG_INF, mlo = NEG_INF, mhi = NEG_INF;
#pragma unroll 4
        for (int u = 0; u < GU; ++u) {
            const int k = k0 + u;
            const ull ap = score_chain(g2p, n2, k, ypd);
            const ull am = score_chain(g2p, n2, k, ymd);
            plo = fmaxf(plo, f2lo(ap));   // FMNMX — no predicates
            phi = fmaxf(phi, f2hi(ap));
            mlo = fmaxf(mlo, f2lo(am));
            mhi = fmaxf(mhi, f2hi(am));
        }
        const float sp = fmaxf(plo, phi);
        if (sp > gbvp) { gbvp = sp; gidp = k0; }
        const float sm_ = fmaxf(mlo, mhi);
        if (sm_ > gbvm) { gbvm = sm_; gidm = k0; }
    }

    // Rescan the winning group per branch; identical fma.rn sequence =>
    // bitwise-equal scores, recover entry index by bit equality.
    int qp = 0, qm = 0;
    {
        const unsigned t = __float_as_uint(gbvp);
        for (int u = 0; u < GU; ++u) {
            const int k = gidp + u;
            const ull a = score_chain(g2p, n2, k, ypd);
            if (__float_as_uint(f2lo(a)) == t) { qp = 2 * k;     break; }
            if (__float_as_uint(f2hi(a)) == t) { qp = 2 * k + 1; break; }
        }
    }
    {
        const unsigned t = __float_as_uint(gbvm);
        for (int u = 0; u < GU; ++u) {
            const int k = gidm + u;
            const ull a = score_chain(g2p, n2, k, ymd);
            if (__float_as_uint(f2lo(a)) == t) { qm = 2 * k;     break; }
            if (__float_as_uint(f2hi(a)) == t) { qm = 2 * k + 1; break; }
        }
    }

    finish_point(p, g2p, G, ypd, ymd, nbp, nbm, qp, qm,
                 idx_map, allcombo, out_vals, out_idx_f);
}

// ---------------------------------------------------------------------------
// Launch. Inputs (metadata order):
//   0: X              float32 [N,8]
//   1: grid_part      float32 [G,8]
//   2: grid_part_norm float32 [G]
//   3: allcombo_idx   int32   [128,G]
//   4: idx_map        int32   [256]
//   5: int_map        int32   [8]      (unused: bit packing hard-coded)
//   6: grid_idx_map   int16->int32 promoted (NOT read; computed analytically)
//
// Output layout (pinned by rounds 0-6):
//   final_vals  float32 [N,8] at element 0   (bit-exact)
//   final_idxs  float32 [N]   at element 8N
// ---------------------------------------------------------------------------
extern "C" void kernel_launch(void* const* d_in, const int* in_sizes, int n_in,
                              void* d_out, int out_size) {
    const float* X        = (const float*)d_in[0];
    const float* grid     = (const float*)d_in[1];
    const float* gnorm    = (const float*)d_in[2];
    const int*   allcombo = (const int*)d_in[3];
    const int*   idx_map  = (const int*)d_in[4];

    const int N = in_sizes[0] / 8;
    const int G = in_sizes[2];
    const int G2 = (G + 1) / 2;
    const int G2r = ((G2 + GU - 1) / GU) * GU;   // pad to group multiple

    float* out_vals  = (float*)d_out;
    float* out_idx_f = (float*)d_out + (size_t)N * 8;

    const size_t smem = (size_t)G2r * 9 * sizeof(ull);   // ~49.5 KB
    cudaFuncSetAttribute(e8p12_kernel,
                         cudaFuncAttributeMaxDynamicSharedMemorySize, (int)smem);

    const int threads = 256;
    // Balanced grid: 148 SMs x 4 CTAs/SM slots, chunked point assignment.
    int ctas = 148 * 4;
    int chunk = (N + ctas - 1) / ctas;
    if (chunk > threads) {                 // very large N fallback
        chunk = threads;
        ctas = (N + threads - 1) / threads;
    }

    e8p12_kernel<<<ctas, threads, smem>>>(X, grid, gnorm, allcombo, idx_map,
                                          out_vals, out_idx_f, N, G, G2r, chunk);
}

// round 15
// speedup vs baseline: 1.5098x; 1.1623x over previous
#include <cuda_runtime.h>
#include <cstdint>

typedef unsigned long long ull;

// ---------------------------------------------------------------------------
// Packed f32x2 helpers (Blackwell packed-fp32 pipe — only reachable via PTX).
// Only fma/add/mul have .f32x2 forms; max does NOT (round-12 ptxas evidence).
// ---------------------------------------------------------------------------
__device__ __forceinline__ ull ffma2(ull a, ull b, ull c) {
    ull d;
    asm("fma.rn.f32x2 %0, %1, %2, %3;" : "=l"(d) : "l"(a), "l"(b), "l"(c));
    return d;
}
__device__ __forceinline__ float f2lo(ull v) { return __uint_as_float((unsigned)(v & 0xffffffffu)); }
__device__ __forceinline__ float f2hi(ull v) { return __uint_as_float((unsigned)(v >> 32)); }
__device__ __forceinline__ ull fpack(float lo, float hi) {
    return ((ull)__float_as_uint(hi) << 32) | (ull)__float_as_uint(lo);
}
__device__ __forceinline__ ull fdup(float v) {
    unsigned u = __float_as_uint(v);
    return ((ull)u << 32) | (ull)u;
}

#define NEG_INF __int_as_float(0xff800000)
#define GU 16   // pairs per group for deferred-index argmax (even!)

// ---------------------------------------------------------------------------
// Packed pair-score chain: 8-deep fma.rn.f32x2 init (-n,-n). The SAME
// function is used in the hot loop and the rescan -> bitwise-identical.
// ---------------------------------------------------------------------------
__device__ __forceinline__ ull score_chain_c(const ulonglong2 c01,
                                             const ulonglong2 c23,
                                             const ulonglong2 c45,
                                             const ulonglong2 c67,
                                             ull nn, const ull y[8]) {
    ull a = ffma2(y[0], c01.x, nn);
    a = ffma2(y[1], c01.y, a);
    a = ffma2(y[2], c23.x, a);
    a = ffma2(y[3], c23.y, a);
    a = ffma2(y[4], c45.x, a);
    a = ffma2(y[5], c45.y, a);
    a = ffma2(y[6], c67.x, a);
    a = ffma2(y[7], c67.y, a);
    return a;
}
__device__ __forceinline__ ull score_chain(const ull* __restrict__ g2p,
                                           const ull* __restrict__ n2,
                                           int k, const ull y[8]) {
    const ulonglong2* gq = reinterpret_cast<const ulonglong2*>(g2p + (size_t)k * 8);
    return score_chain_c(gq[0], gq[1], gq[2], gq[3], n2[k], y);
}

// ---------------------------------------------------------------------------
// Per-point prep: |Y| for both branches with the odd-parity coord-0 flip and
// sign bitmasks. Duplicated into both f32x2 lanes (lanes = grid-entry pair).
// ---------------------------------------------------------------------------
__device__ __forceinline__ void prep_point(const float* __restrict__ Xp,
                                           ull ypd[8], ull ymd[8],
                                           unsigned& nbp, unsigned& nbm) {
    float4 x0 = *reinterpret_cast<const float4*>(Xp);
    float4 x1 = *reinterpret_cast<const float4*>(Xp + 4);
    float x[8] = {x0.x, x0.y, x0.z, x0.w, x1.x, x1.y, x1.z, x1.w};
    float yp[8], ym[8];
    unsigned bp = 0u, bm = 0u;
#pragma unroll
    for (int i = 0; i < 8; i++) {
        float a = x[i] + 0.25f;
        float b = x[i] - 0.25f;
        bp |= (a < 0.0f ? 1u : 0u) << (7 - i);
        bm |= (b < 0.0f ? 1u : 0u) << (7 - i);
        yp[i] = fabsf(a);
        ym[i] = fabsf(b);
    }
    if (__popc(bp) & 1) { yp[0] = -yp[0]; bp ^= 0x80u; }
    if (__popc(bm) & 1) { ym[0] = -ym[0]; bm ^= 0x80u; }
#pragma unroll
    for (int i = 0; i < 8; i++) { ypd[i] = fdup(yp[i]); ymd[i] = fdup(ym[i]); }
    nbp = bp;
    nbm = bm;
}

// Read coord i of entry q from the pair layout (stored as 2*g; *0.5 exact).
__device__ __forceinline__ float grid_coord(const ull* __restrict__ g2p,
                                            int q, int i) {
    ull w = g2p[(size_t)(q >> 1) * 8 + i];
    return ((q & 1) ? f2hi(w) : f2lo(w)) * 0.5f;
}

// Rescan the winning GU-pair group: bitwise-equal score match -> entry index.
__device__ __forceinline__ int rescan_group(const ull* __restrict__ g2p,
                                            const ull* __restrict__ n2,
                                            int k0, float best, const ull y[8]) {
    const unsigned t = __float_as_uint(best);
    for (int u = 0; u < GU; ++u) {
        const int k = k0 + u;
        const ull a = score_chain(g2p, n2, k, y);
        if (__float_as_uint(f2lo(a)) == t) return 2 * k;
        if (__float_as_uint(f2hi(a)) == t) return 2 * k + 1;
    }
    return 2 * k0;   // unreachable (max must be in its group)
}

// ---------------------------------------------------------------------------
// Epilogue: reconstruct both branch errors/values, pick branch, index lookups
// (grid_idx_map analytically: gim[j] = j - 32768; int16 input is promoted to
// int32 by the harness so unreadable as shorts). idx region is float32 at
// element 8N (round-4 NaN evidence).
// ---------------------------------------------------------------------------
__device__ __forceinline__ void finish_point(
    int p, const ull* __restrict__ g2p, int G,
    const ull ypd[8], const ull ymd[8],
    unsigned nbp, unsigned nbm, int qp, int qm,
    const int* __restrict__ idx_map, const int* __restrict__ allcombo,
    float* __restrict__ out_vals, float* __restrict__ out_idx_f) {
    float pv[8], mv[8];
    float ep2 = 0.0f, em2 = 0.0f;
#pragma unroll
    for (int i = 0; i < 8; i++) {
        float gp_ = grid_coord(g2p, qp, i);
        float gm_ = grid_coord(g2p, qm, i);
        float dp = f2lo(ypd[i]) - gp_;    // == +/-(Y - vals): square bit-identical
        float dm = f2lo(ymd[i]) - gm_;
        ep2 = fmaf(dp, dp, ep2);
        em2 = fmaf(dm, dm, em2);
        pv[i] = ((nbp >> (7 - i)) & 1u) ? -gp_ : gp_;
        mv[i] = ((nbm >> (7 - i)) & 1u) ? -gm_ : gm_;
    }
    bool which = sqrtf(ep2) < sqrtf(em2);   // matches reference

    int rowp = __ldg(&idx_map[nbp]);
    int rowm = __ldg(&idx_map[nbm]);
    int pi = __ldg(&allcombo[(size_t)rowp * G + qp]);
    int mi = __ldg(&allcombo[(size_t)rowm * G + qm]);
    int j = which ? (pi + 32768) : mi;
    if (j > 65535) j = 65535;               // JAX clamps OOB gather indices
    int idx = j - 32768;                    // == grid_idx_map[j] analytically

    float ov[8];
#pragma unroll
    for (int i = 0; i < 8; i++) ov[i] = which ? (pv[i] - 0.25f) : (mv[i] + 0.25f);
    float4* ovp = reinterpret_cast<float4*>(out_vals + (size_t)p * 8);
    ovp[0] = make_float4(ov[0], ov[1], ov[2], ov[3]);
    ovp[1] = make_float4(ov[4], ov[5], ov[6], ov[7]);

    out_idx_f[p] = (float)idx;
}

// ---------------------------------------------------------------------------
// Main kernel. Entry-pair f32x2 lanes (round-14 win) + TWO points per thread
// so the LDS stream is shared across 8 scores per 2-pair block (round-14 ncu:
// L1=68.7% was the wall at 1.25 LDS/score; this gives 0.56). Tree fmaxf
// group-max + deferred rescan. Warp-aligned split: warps whose threads all
// have one point run a cheaper single-point body.
// ---------------------------------------------------------------------------
__global__ void __launch_bounds__(256, 2)
e8p12_kernel(const float* __restrict__ X,
             const float* __restrict__ grid,
             const float* __restrict__ gnorm,
             const int*   __restrict__ allcombo,
             const int*   __restrict__ idx_map,
             float* __restrict__ out_vals,
             float* __restrict__ out_idx_f,
             int N, int G, int G2r, int chunk) {
    extern __shared__ ull sm_u64[];
    ull* g2p = sm_u64;                      // [G2r*8] coord words (2g_e0, 2g_e1)
    ull* n2  = sm_u64 + (size_t)G2r * 8;    // [G2r]   (-n_e0, -n_e1); pad=-inf

    const int tid = threadIdx.x;
    for (int j = tid; j < G2r * 8; j += blockDim.x) {
        int k = j >> 3, i = j & 7;
        int e0 = 2 * k, e1 = 2 * k + 1;
        float lo = (e0 < G) ? 2.0f * grid[(size_t)e0 * 8 + i] : 0.0f;
        float hi = (e1 < G) ? 2.0f * grid[(size_t)e1 * 8 + i] : 0.0f;
        g2p[j] = fpack(lo, hi);
    }
    for (int k = tid; k < G2r; k += blockDim.x) {
        int e0 = 2 * k, e1 = 2 * k + 1;
        float lo = (e0 < G) ? -gnorm[e0] : NEG_INF;   // pad never wins
        float hi = (e1 < G) ? -gnorm[e1] : NEG_INF;
        n2[k] = fpack(lo, hi);
    }
    __syncthreads();

    const int b0 = blockIdx.x * chunk;
    if (b0 >= N) return;
    const int len = min(chunk, N - b0);
    const int t2 = len - 256;                      // threads with a 2nd point
    const int twoWarps = (t2 > 0) ? ((t2 + 31) >> 5) : 0;

    if ((tid >> 5) < twoWarps) {
        // ------------------- two-point body -------------------
        const int pA = b0 + tid;
        const bool haveB = (tid + 256) < len;      // pB < N follows (b0+len<=N)
        const int pB = haveB ? (pA + 256) : pA;

        ull yApd[8], yAmd[8], yBpd[8], yBmd[8];
        unsigned nbpA, nbmA, nbpB, nbmB;
        prep_point(X + (size_t)pA * 8, yApd, yAmd, nbpA, nbmA);
        prep_point(X + (size_t)pB * 8, yBpd, yBmd, nbpB, nbmB);

        float gbPA = NEG_INF, gbMA = NEG_INF, gbPB = NEG_INF, gbMB = NEG_INF;
        int giPA = 0, giMA = 0, giPB = 0, giMB = 0;

        for (int k0 = 0; k0 < G2r; k0 += GU) {
            float aPA = NEG_INF, aMA = NEG_INF, aPB = NEG_INF, aMB = NEG_INF;
            for (int u = 0; u < GU; u += 2) {
                const int k = k0 + u;
                const ulonglong2 nn2 =
                    *reinterpret_cast<const ulonglong2*>(n2 + k);  // 2 norms, 1 LDS.128
                const ulonglong2* gq =
                    reinterpret_cast<const ulonglong2*>(g2p + (size_t)k * 8);
                const ulonglong2 c01 = gq[0], c23 = gq[1];
                const ulonglong2 c45 = gq[2], c67 = gq[3];
                const ulonglong2 d01 = gq[4], d23 = gq[5];
                const ulonglong2 d45 = gq[6], d67 = gq[7];

                ull s;
                s = score_chain_c(c01, c23, c45, c67, nn2.x, yApd);
                aPA = fmaxf(aPA, fmaxf(f2lo(s), f2hi(s)));
                s = score_chain_c(c01, c23, c45, c67, nn2.x, yAmd);
                aMA = fmaxf(aMA, fmaxf(f2lo(s), f2hi(s)));
                s = score_chain_c(c01, c23, c45, c67, nn2.x, yBpd);
                aPB = fmaxf(aPB, fmaxf(f2lo(s), f2hi(s)));
                s = score_chain_c(c01, c23, c45, c67, nn2.x, yBmd);
                aMB = fmaxf(aMB, fmaxf(f2lo(s), f2hi(s)));

                s = score_chain_c(d01, d23, d45, d67, nn2.y, yApd);
                aPA = fmaxf(aPA, fmaxf(f2lo(s), f2hi(s)));
                s = score_chain_c(d01, d23, d45, d67, nn2.y, yAmd);
                aMA = fmaxf(aMA, fmaxf(f2lo(s), f2hi(s)));
                s = score_chain_c(d01, d23, d45, d67, nn2.y, yBpd);
                aPB = fmaxf(aPB, fmaxf(f2lo(s), f2hi(s)));
                s = score_chain_c(d01, d23, d45, d67, nn2.y, yBmd);
                aMB = fmaxf(aMB, fmaxf(f2lo(s), f2hi(s)));
            }
            if (aPA > gbPA) { gbPA = aPA; giPA = k0; }
            if (aMA > gbMA) { gbMA = aMA; giMA = k0; }
            if (aPB > gbPB) { gbPB = aPB; giPB = k0; }
            if (aMB > gbMB) { gbMB = aMB; giMB = k0; }
        }

        const int qpA = rescan_group(g2p, n2, giPA, gbPA, yApd);
        const int qmA = rescan_group(g2p, n2, giMA, gbMA, yAmd);
        finish_point(pA, g2p, G, yApd, yAmd, nbpA, nbmA, qpA, qmA,
                     idx_map, allcombo, out_vals, out_idx_f);
        if (haveB) {
            const int qpB = rescan_group(g2p, n2, giPB, gbPB, yBpd);
            const int qmB = rescan_group(g2p, n2, giMB, gbMB, yBmd);
            finish_point(pB, g2p, G, yBpd, yBmd, nbpB, nbmB, qpB, qmB,
                         idx_map, allcombo, out_vals, out_idx_f);
        }
    } else {
        // ------------------- single-point body -------------------
        const int p = b0 + tid;
        if (tid >= len || p >= N) return;

        ull ypd[8], ymd[8];
        unsigned nbp, nbm;
        prep_point(X + (size_t)p * 8, ypd, ymd, nbp, nbm);

        float gbP = NEG_INF, gbM = NEG_INF;
        int giP = 0, giM = 0;

        for (int k0 = 0; k0 < G2r; k0 += GU) {
            float aP = NEG_INF, aM = NEG_INF;
            for (int u = 0; u < GU; u += 2) {
                const int k = k0 + u;
                const ulonglong2 nn2 =
                    *reinterpret_cast<const ulonglong2*>(n2 + k);
                const ulonglong2* gq =
                    reinterpret_cast<const ulonglong2*>(g2p + (size_t)k * 8);
                const ulonglong2 c01 = gq[0], c23 = gq[1];
                const ulonglong2 c45 = gq[2], c67 = gq[3];
                const ulonglong2 d01 = gq[4], d23 = gq[5];
                const ulonglong2 d45 = gq[6], d67 = gq[7];

                ull s;
                s = score_chain_c(c01, c23, c45, c67, nn2.x, ypd);
                aP = fmaxf(aP, fmaxf(f2lo(s), f2hi(s)));
                s = score_chain_c(c01, c23, c45, c67, nn2.x, ymd);
                aM = fmaxf(aM, fmaxf(f2lo(s), f2hi(s)));
                s = score_chain_c(d01, d23, d45, d67, nn2.y, ypd);
                aP = fmaxf(aP, fmaxf(f2lo(s), f2hi(s)));
                s = score_chain_c(d01, d23, d45, d67, nn2.y, ymd);
                aM = fmaxf(aM, fmaxf(f2lo(s), f2hi(s)));
            }
            if (aP > gbP) { gbP = aP; giP = k0; }
            if (aM > gbM) { gbM = aM; giM = k0; }
        }

        const int qp = rescan_group(g2p, n2, giP, gbP, ypd);
        const int qm = rescan_group(g2p, n2, giM, gbM, ymd);
        finish_point(p, g2p, G, ypd, ymd, nbp, nbm, qp, qm,
                     idx_map, allcombo, out_vals, out_idx_f);
    }
}

// ---------------------------------------------------------------------------
// Launch. Inputs (metadata order):
//   0: X              float32 [N,8]
//   1: grid_part      float32 [G,8]
//   2: grid_part_norm float32 [G]
//   3: allcombo_idx   int32   [128,G]
//   4: idx_map        int32   [256]
//   5: int_map        int32   [8]      (unused)
//   6: grid_idx_map   int16->int32 promoted (NOT read; analytic)
//
// Output: final_vals float32 [N,8] @0 (bit-exact), final_idxs float32 [N] @8N.
// Grid: 296 CTAs (2/SM, no wave imbalance), ~443 points/CTA, 2 points/thread
// for warps fully inside the chunk.
// ---------------------------------------------------------------------------
extern "C" void kernel_launch(void* const* d_in, const int* in_sizes, int n_in,
                              void* d_out, int out_size) {
    const float* X        = (const float*)d_in[0];
    const float* grid     = (const float*)d_in[1];
    const float* gnorm    = (const float*)d_in[2];
    const int*   allcombo = (const int*)d_in[3];
    const int*   idx_map  = (const int*)d_in[4];

    const int N = in_sizes[0] / 8;
    const int G = in_sizes[2];
    const int G2 = (G + 1) / 2;
    const int G2r = ((G2 + GU - 1) / GU) * GU;   // pad to group multiple

    float* out_vals  = (float*)d_out;
    float* out_idx_f = (float*)d_out + (size_t)N * 8;

    const size_t smem = (size_t)G2r * 9 * sizeof(ull);   // ~49.5 KB
    cudaFuncSetAttribute(e8p12_kernel,
                         cudaFuncAttributeMaxDynamicSharedMemorySize, (int)smem);

    const int threads = 256;
    int ctas = 2 * 148;                          // 2 CTAs/SM, balanced
    int chunk = (N + ctas - 1) / ctas;           // ~443 for N=131072
    if (chunk > 2 * threads) {                   // huge-N fallback
        chunk = 2 * threads;
        ctas = (N + chunk - 1) / chunk;
    }

    e8p12_kernel<<<ctas, threads, smem>>>(X, grid, gnorm, allcombo, idx_map,
                                          out_vals, out_idx_f, N, G, G2r, chunk);
}